// round 6
// baseline (speedup 1.0000x reference)
#include <cuda_runtime.h>
#include <cstdint>

// Problem constants
#define Bx    8
#define Cx    256
#define Kx    19
#define HW4   4096          // HW / 4 (float4 units), HW = 128*128
#define RC    4             // c-rows per warp
#define WARPS 4
#define CG    (WARPS*RC)    // 16 c-rows per block
#define NCG   (Cx/CG)       // 16
#define CH    32            // float4 columns per smem chunk
#define NCHT  (HW4/CH)      // 128 chunks per (b,cgroup)
#define Sx    7             // hw splits -> grid 896 ~ 3 waves @ 2 blk/SM

// Scratch: att quarter-partials [s][b][c][k][quarter(4)]
__device__ float g_att_part[Sx * Bx * Cx * Kx * 4];

// ---- cp.async helpers ------------------------------------------------------
__device__ __forceinline__ void cp_async16(uint32_t saddr, const void* gptr) {
    asm volatile("cp.async.cg.shared.global [%0], [%1], 16;\n" :: "r"(saddr), "l"(gptr));
}
__device__ __forceinline__ void cp_commit() {
    asm volatile("cp.async.commit_group;\n");
}
template <int N>
__device__ __forceinline__ void cp_wait() {
    asm volatile("cp.async.wait_group %0;\n" :: "n"(N));
}
__device__ __forceinline__ uint32_t smem_u32(const void* p) {
    return (uint32_t)__cvta_generic_to_shared(p);
}
// Packed dual-FMA: acc(f32x2) += a(f32x2) * b(f32x2)   [Blackwell FFMA2]
__device__ __forceinline__ void ffma2(unsigned long long& acc,
                                      unsigned long long a, unsigned long long b) {
    asm("fma.rn.f32x2 %0, %1, %2, %0;" : "+l"(acc) : "l"(a), "l"(b));
}

// ---------------------------------------------------------------------------
// Kernel 1: att partials. Map chunks double-buffered through smem (cp.async,
// buffer parity == global chunk parity). Feature prefetched one chunk ahead
// into plain register arrays (constant-indexed only — NEVER passed as array
// arguments; that decays to a pointer and demotes them to local memory,
// which was the R3/R4 regression).
// ---------------------------------------------------------------------------
__global__ __launch_bounds__(128)
void k_att(const float* __restrict__ feat, const float* __restrict__ map) {
    __shared__ float4 smap[2][Kx * CH];            // 2 x 9728 B

    const int bid  = blockIdx.x;
    const int s    = bid % Sx;
    const int cg   = (bid / Sx) % NCG;
    const int b    = bid / (Sx * NCG);
    const int tid  = threadIdx.x;
    const int w    = tid >> 5;
    const int lane = tid & 31;
    const int c0   = cg * CG + w * RC;

    const int ch_beg = (s * NCHT) / Sx;            // 18/19-chunk ranges
    const int ch_end = ((s + 1) * NCHT) / Sx;

    const float4* __restrict__ f4 = (const float4*)feat;
    const float4* __restrict__ m4 = (const float4*)map;
    const float4* fbase = f4 + (size_t)(b * Cx + c0) * HW4;
    const float4* mbase = m4 + (size_t)(b * Kx) * HW4;

    unsigned long long acc2[Kx * RC];
    #pragma unroll
    for (int i = 0; i < Kx * RC; i++) acc2[i] = 0ull;

    // map-chunk loader: 19*32 = 608 float4 by 128 threads (smem writes only)
    auto load_map_chunk = [&](int buf, int chunk) {
        const float4* src = mbase + chunk * CH;
        uint32_t sb = smem_u32(&smap[buf][0]);
        #pragma unroll
        for (int j = 0; j < 4; j++) {
            int e = tid + j * 128;                 // e = k*CH + col
            cp_async16(sb + e * 16, src + (size_t)(e >> 5) * HW4 + (e & 31));
        }
        if (tid < Kx * CH - 512) {
            int e = tid + 512;
            cp_async16(sb + e * 16, src + (size_t)(e >> 5) * HW4 + (e & 31));
        }
    };

    ulonglong2 fc[RC], fn[RC];                     // register-resident prefetch

    load_map_chunk(ch_beg & 1, ch_beg);
    cp_commit();
    {
        const int col = ch_beg * CH + lane;
        #pragma unroll
        for (int c = 0; c < RC; c++)
            fc[c] = *(const ulonglong2*)(fbase + (size_t)c * HW4 + col);
    }

    #pragma unroll 1
    for (int ch = ch_beg; ch < ch_end; ch++) {
        const bool more = (ch + 1 < ch_end);
        if (more) { load_map_chunk((ch + 1) & 1, ch + 1); cp_commit(); }
        if (more) cp_wait<1>(); else cp_wait<0>();
        __syncthreads();

        if (more) {                                // LDG covered by FFMA2 burst
            const int col = (ch + 1) * CH + lane;
            #pragma unroll
            for (int c = 0; c < RC; c++)
                fn[c] = *(const ulonglong2*)(fbase + (size_t)c * HW4 + col);
        }

        const float4* sb = smap[ch & 1];
        #pragma unroll
        for (int k = 0; k < Kx; k++) {
            ulonglong2 mv = *(const ulonglong2*)(&sb[k * CH + lane]);
            #pragma unroll
            for (int c = 0; c < RC; c++)
                ffma2(acc2[k * RC + c], fc[c].x, mv.x);
            #pragma unroll
            for (int c = 0; c < RC; c++)
                ffma2(acc2[k * RC + c], fc[c].y, mv.y);
        }
        __syncthreads();                           // protect smem before overwrite
        #pragma unroll
        for (int c = 0; c < RC; c++) fc[c] = fn[c];
    }

    // Collapse packed pairs; 3-round lane reduction -> quarter partials.
    #pragma unroll
    for (int i = 0; i < Kx * RC; i++) {
        float lo = __uint_as_float((uint32_t)acc2[i]);
        float hi = __uint_as_float((uint32_t)(acc2[i] >> 32));
        float v = lo + hi;
        v += __shfl_down_sync(0xffffffffu, v, 16);
        v += __shfl_down_sync(0xffffffffu, v, 8);
        v += __shfl_down_sync(0xffffffffu, v, 4);
        acc2[i] = (unsigned long long)__float_as_uint(v);
    }

    if (lane < 4) {
        #pragma unroll
        for (int c = 0; c < RC; c++)
            #pragma unroll
            for (int k = 0; k < Kx; k++) {
                float v = __uint_as_float((uint32_t)acc2[k * RC + c]);
                g_att_part[((((size_t)s * Bx + b) * Cx + (c0 + c)) * Kx + k) * 4 + lane] = v;
            }
    }
}

// ---------------------------------------------------------------------------
// Kernel 2 (fused scale+apply): one block per (b,c) row.
// ---------------------------------------------------------------------------
__global__ __launch_bounds__(256)
void k_apply(const float* __restrict__ feat, const float* __restrict__ gamma,
             float* __restrict__ out) {
    __shared__ float sh[Kx + 1];
    const int row = blockIdx.x;                    // b*Cx + c
    const int tid = threadIdx.x;

    if (tid < Kx) {
        const float* p = g_att_part + (size_t)row * Kx * 4 + tid * 4;
        float a = 0.f;
        #pragma unroll
        for (int s = 0; s < Sx; s++) {
            const float* ps = p + (size_t)s * Bx * Cx * Kx * 4;
            a += ps[0] + ps[1] + ps[2] + ps[3];
        }
        sh[tid] = gamma[tid] * (1.f / (1.f + __expf(-a)));
    }
    __syncthreads();
    if (tid == 0) {
        float sc = 0.f;
        #pragma unroll
        for (int k = 0; k < Kx; k++) sc += sh[k];
        sh[Kx] = 1.f + sc;
    }
    __syncthreads();
    const float s = sh[Kx];

    const float4* __restrict__ fr = (const float4*)feat + (size_t)row * HW4;
    float4* __restrict__ orow = (float4*)out + (size_t)row * HW4;
    #pragma unroll 4
    for (int i = tid; i < HW4; i += 256) {
        float4 f = __ldcs(fr + i);                 // last consumer: evict-first
        f.x *= s; f.y *= s; f.z *= s; f.w *= s;
        __stcs(orow + i, f);                       // single-use output stream
    }
}

// ---------------------------------------------------------------------------
extern "C" void kernel_launch(void* const* d_in, const int* in_sizes, int n_in,
                              void* d_out, int out_size) {
    const float* feat  = (const float*)d_in[0];
    const float* map_  = (const float*)d_in[1];
    const float* gamma = (const float*)d_in[2];
    float* out = (float*)d_out;

    k_att  <<<Bx * NCG * Sx, 128>>>(feat, map_);
    k_apply<<<Bx * Cx, 256>>>(feat, gamma, out);
}

// round 7
// speedup vs baseline: 1.0066x; 1.0066x over previous
#include <cuda_runtime.h>
#include <cstdint>

// Problem constants
#define Bx    8
#define Cx    256
#define Kx    19
#define HW4   4096          // HW / 4 (float4 units), HW = 128*128
#define RC    4             // c-rows per warp
#define WARPS 4
#define CG    (WARPS*RC)    // 16 c-rows per block
#define NCG   (Cx/CG)       // 16
#define CH    32            // float4 columns per smem chunk
#define NCHT  (HW4/CH)      // 128 chunks total
#define Sx    7             // hw splits -> grid 896 ~ 3 waves @ 2 blk/SM
#define NBUF  4             // cp.async ring depth (prefetch distance 3)

// Scratch: att quarter-partials [s][b][c][k][quarter(4)]
__device__ float g_att_part[Sx * Bx * Cx * Kx * 4];

// ---- cp.async helpers ------------------------------------------------------
__device__ __forceinline__ void cp_async16(uint32_t saddr, const void* gptr) {
    asm volatile("cp.async.cg.shared.global [%0], [%1], 16;\n" :: "r"(saddr), "l"(gptr));
}
__device__ __forceinline__ void cp_commit() {
    asm volatile("cp.async.commit_group;\n");
}
template <int N>
__device__ __forceinline__ void cp_wait() {
    asm volatile("cp.async.wait_group %0;\n" :: "n"(N));
}
__device__ __forceinline__ uint32_t smem_u32(const void* p) {
    return (uint32_t)__cvta_generic_to_shared(p);
}
// Packed dual-FMA: acc(f32x2) += a(f32x2) * b(f32x2)   [Blackwell FFMA2]
__device__ __forceinline__ void ffma2(unsigned long long& acc,
                                      unsigned long long a, unsigned long long b) {
    asm("fma.rn.f32x2 %0, %1, %2, %0;" : "+l"(acc) : "l"(a), "l"(b));
}

// ---------------------------------------------------------------------------
// Kernel 1: att partials. Map chunks staged through a 4-deep cp.async ring
// (prefetch distance 3 -> ~3 chunk-times of DRAM-latency cover, vs 1 with the
// old double buffer). One barrier per chunk. Invariants:
//   - group committed at iter ch covers chunk ch+3 (possibly empty past end)
//   - cp_wait<2> at iter ch retires exactly chunk ch's group
//   - buffer (ch+3)%4 == (ch-1)%4 is only rewritten AFTER the barrier that
//     proves all warps finished computing chunk ch-1.
// ---------------------------------------------------------------------------
__global__ __launch_bounds__(128)
void k_att(const float* __restrict__ feat, const float* __restrict__ map) {
    __shared__ float4 smap[NBUF][Kx * CH];         // 4 x 9728 B = 38.9 KB

    const int bid  = blockIdx.x;
    const int s    = bid % Sx;
    const int cg   = (bid / Sx) % NCG;
    const int b    = bid / (Sx * NCG);
    const int tid  = threadIdx.x;
    const int w    = tid >> 5;
    const int lane = tid & 31;
    const int c0   = cg * CG + w * RC;

    const int ch_beg = (s * NCHT) / Sx;            // 18/19-chunk ranges
    const int ch_end = ((s + 1) * NCHT) / Sx;

    const float4* __restrict__ f4 = (const float4*)feat;
    const float4* __restrict__ m4 = (const float4*)map;
    const float4* fbase = f4 + (size_t)(b * Cx + c0) * HW4;
    const float4* mbase = m4 + (size_t)(b * Kx) * HW4;

    unsigned long long acc2[Kx * RC];
    #pragma unroll
    for (int i = 0; i < Kx * RC; i++) acc2[i] = 0ull;

    // map-chunk loader: 19*32 = 608 float4 by 128 threads (smem writes only)
    auto load_map_chunk = [&](int chunk) {
        const float4* src = mbase + chunk * CH;
        uint32_t sb = smem_u32(&smap[chunk & (NBUF - 1)][0]);
        #pragma unroll
        for (int j = 0; j < 4; j++) {
            int e = tid + j * 128;                 // e = k*CH + col
            cp_async16(sb + e * 16, src + (size_t)(e >> 5) * HW4 + (e & 31));
        }
        if (tid < Kx * CH - 512) {
            int e = tid + 512;
            cp_async16(sb + e * 16, src + (size_t)(e >> 5) * HW4 + (e & 31));
        }
    };

    // Prologue: 3 groups in flight (chunks ch_beg .. ch_beg+2).
    #pragma unroll
    for (int p = 0; p < NBUF - 1; p++) {
        if (ch_beg + p < ch_end) load_map_chunk(ch_beg + p);
        cp_commit();
    }

    ulonglong2 fc[RC], fn[RC];                     // register-resident feature
    {
        const int col = ch_beg * CH + lane;
        #pragma unroll
        for (int c = 0; c < RC; c++)
            fc[c] = *(const ulonglong2*)(fbase + (size_t)c * HW4 + col);
    }

    #pragma unroll 1
    for (int ch = ch_beg; ch < ch_end; ch++) {
        cp_wait<NBUF - 2>();                       // chunk ch's data resident
        __syncthreads();                           // all warps done with ch-1

        if (ch + NBUF - 1 < ch_end) load_map_chunk(ch + NBUF - 1);
        cp_commit();                               // commit even if empty

        const bool more = (ch + 1 < ch_end);
        if (more) {                                // LDG covered by FFMA2 burst
            const int col = (ch + 1) * CH + lane;
            #pragma unroll
            for (int c = 0; c < RC; c++)
                fn[c] = *(const ulonglong2*)(fbase + (size_t)c * HW4 + col);
        }

        const float4* sb = smap[ch & (NBUF - 1)];
        #pragma unroll
        for (int k = 0; k < Kx; k++) {
            ulonglong2 mv = *(const ulonglong2*)(&sb[k * CH + lane]);
            #pragma unroll
            for (int c = 0; c < RC; c++)
                ffma2(acc2[k * RC + c], fc[c].x, mv.x);
            #pragma unroll
            for (int c = 0; c < RC; c++)
                ffma2(acc2[k * RC + c], fc[c].y, mv.y);
        }
        #pragma unroll
        for (int c = 0; c < RC; c++) fc[c] = fn[c];
    }

    // Collapse packed pairs; 3-round lane reduction -> quarter partials.
    #pragma unroll
    for (int i = 0; i < Kx * RC; i++) {
        float lo = __uint_as_float((uint32_t)acc2[i]);
        float hi = __uint_as_float((uint32_t)(acc2[i] >> 32));
        float v = lo + hi;
        v += __shfl_down_sync(0xffffffffu, v, 16);
        v += __shfl_down_sync(0xffffffffu, v, 8);
        v += __shfl_down_sync(0xffffffffu, v, 4);
        acc2[i] = (unsigned long long)__float_as_uint(v);
    }

    if (lane < 4) {
        #pragma unroll
        for (int c = 0; c < RC; c++)
            #pragma unroll
            for (int k = 0; k < Kx; k++) {
                float v = __uint_as_float((uint32_t)acc2[k * RC + c]);
                g_att_part[((((size_t)s * Bx + b) * Cx + (c0 + c)) * Kx + k) * 4 + lane] = v;
            }
    }
}

// ---------------------------------------------------------------------------
// Kernel 2 (fused scale+apply): one block per (b,c) row. Plain loads/stores
// (streaming hints measured slower in R5).
// ---------------------------------------------------------------------------
__global__ __launch_bounds__(256)
void k_apply(const float* __restrict__ feat, const float* __restrict__ gamma,
             float* __restrict__ out) {
    __shared__ float sh[Kx + 1];
    const int row = blockIdx.x;                    // b*Cx + c
    const int tid = threadIdx.x;

    if (tid < Kx) {
        const float* p = g_att_part + (size_t)row * Kx * 4 + tid * 4;
        float a = 0.f;
        #pragma unroll
        for (int s = 0; s < Sx; s++) {
            const float* ps = p + (size_t)s * Bx * Cx * Kx * 4;
            a += ps[0] + ps[1] + ps[2] + ps[3];
        }
        sh[tid] = gamma[tid] * (1.f / (1.f + __expf(-a)));
    }
    __syncthreads();
    if (tid == 0) {
        float sc = 0.f;
        #pragma unroll
        for (int k = 0; k < Kx; k++) sc += sh[k];
        sh[Kx] = 1.f + sc;
    }
    __syncthreads();
    const float s = sh[Kx];

    const float4* __restrict__ fr = (const float4*)feat + (size_t)row * HW4;
    float4* __restrict__ orow = (float4*)out + (size_t)row * HW4;
    #pragma unroll 4
    for (int i = tid; i < HW4; i += 256) {
        float4 f = fr[i];
        f.x *= s; f.y *= s; f.z *= s; f.w *= s;
        orow[i] = f;
    }
}

// ---------------------------------------------------------------------------
extern "C" void kernel_launch(void* const* d_in, const int* in_sizes, int n_in,
                              void* d_out, int out_size) {
    const float* feat  = (const float*)d_in[0];
    const float* map_  = (const float*)d_in[1];
    const float* gamma = (const float*)d_in[2];
    float* out = (float*)d_out;

    k_att  <<<Bx * NCG * Sx, 128>>>(feat, map_);
    k_apply<<<Bx * Cx, 256>>>(feat, gamma, out);
}